// round 9
// baseline (speedup 1.0000x reference)
#include <cuda_runtime.h>
#include <cstdint>

// Problem constants
#define NB   4
#define CC   64
#define HH   256
#define WW   448
#define HWSZ (HH * WW)            // 114688
#define KCAP 32                   // max entries per target (Poisson(4) tail ~1e-24)

#define NTSP (HWSZ / 32)          // 3584 transpose blocks (32 px each)
#define NBLD (HWSZ / 256)         // 448 build blocks
#define NGTH (HWSZ / 32)          // 3584 gather blocks (32 targets each)

// Scratch (static zero-init; gather re-zeroes g_cnt behind itself so every
// kernel_launch starts from the same state -> graph replays deterministic).
// Entry layout is TRANSPOSED: slot-major, so slot i of target t lives at
// g_ent[i*HWSZ + t] -> warp-uniform entry loads in gather.
__device__ float g_tin[(size_t)HWSZ * 64];     // transposed input [pix][64ch] ~29.4 MB
__device__ int   g_cnt[HWSZ];                  // entries per target
__device__ uint2 g_ent[(size_t)KCAP * HWSZ];   // [slot][target] {src_pix, wgt*exp(metric)}

// ---------------------------------------------------------------------------
// Part A: transpose 32 px x 64 ch tile, NCHW -> channel-last.
// ---------------------------------------------------------------------------
__device__ __forceinline__ void transpose_body(
    const float* __restrict__ inp, int p0, float (*s)[65])
{
    const int tid  = threadIdx.x;
    const int lane = tid & 31;
    const int wa   = tid >> 5;

    #pragma unroll
    for (int k = 0; k < 8; k++) {
        int ch = wa + k * 8;
        s[lane][ch] = __ldcs(inp + (size_t)ch * HWSZ + p0 + lane);
    }
    __syncthreads();

    float4* tb = reinterpret_cast<float4*>(g_tin) + (size_t)p0 * 16;
    #pragma unroll
    for (int k = 0; k < 2; k++) {
        int i  = tid + k * 256;
        int px = i >> 4;
        int f4 = i & 15;
        tb[i] = make_float4(s[px][f4 * 4 + 0], s[px][f4 * 4 + 1],
                            s[px][f4 * 4 + 2], s[px][f4 * 4 + 3]);
    }
}

// ---------------------------------------------------------------------------
// Part B: build per-target entry lists (slot-major layout).
// ---------------------------------------------------------------------------
__device__ __forceinline__ void build_body(
    const float* __restrict__ flow,
    const float* __restrict__ metric, int p0)
{
    const int p = p0 + threadIdx.x;
    const int h = p / WW;
    const int w = p - h * WW;

    float fx = __ldcs(flow + p);
    float fy = __ldcs(flow + HWSZ + p);
    float m  = expf(__ldcs(metric + p));

    float xx  = (float)w + fx;
    float yy  = (float)h + fy;
    float x0f = floorf(xx);
    float y0f = floorf(yy);
    int   x0  = (int)x0f;
    int   y0  = (int)y0f;
    float ax  = xx - x0f;
    float ay  = yy - y0f;

    float wgt[4];
    wgt[0] = (1.f - ax) * (1.f - ay);
    wgt[1] = ax * (1.f - ay);
    wgt[2] = (1.f - ax) * ay;
    wgt[3] = ax * ay;

    #pragma unroll
    for (int j = 0; j < 4; j++) {
        int xi = x0 + (j & 1);
        int yi = y0 + (j >> 1);
        if (((unsigned)xi < (unsigned)WW) && ((unsigned)yi < (unsigned)HH)) {
            int t   = yi * WW + xi;
            int pos = atomicAdd(&g_cnt[t], 1);
            if (pos < KCAP) {
                g_ent[(size_t)pos * HWSZ + t] =
                    make_uint2((unsigned)p, __float_as_uint(wgt[j] * m));
            }
        }
    }
}

// ---------------------------------------------------------------------------
// Fused transpose+build (independent work, disjoint outputs).
// ---------------------------------------------------------------------------
__global__ __launch_bounds__(256) void tb_kernel(
    const float* __restrict__ inp,
    const float* __restrict__ flow,
    const float* __restrict__ metric)
{
    __shared__ float s[32][65];
    if (blockIdx.x < NTSP) {
        transpose_body(inp, blockIdx.x * 32, s);
    } else {
        build_body(flow, metric, (blockIdx.x - NTSP) * 256);
    }
}

// ---------------------------------------------------------------------------
// Gather: 32 targets per block (8 warps x 4 targets). __launch_bounds__(256,2)
// unlocks ~128 regs so the explicit 3-phase chunks can hold 16 entries + 16
// float2 rows in registers: phase1 = 16 entry loads, phase2 = 16 data loads
// (MLP=16 by construction), phase3 = FMAs. Slots 4-7 run under a warp-uniform
// nmax guard. Dead slots use selp weight 0 + row-0 redirect (L1-resident).
// No atomics. Re-zeroes g_cnt behind itself.
// ---------------------------------------------------------------------------
__global__ __launch_bounds__(256, 2) void gather_kernel(float* __restrict__ out)
{
    __shared__ float s_out[32][65];
    __shared__ int   s_cnt[32];

    const int tid  = threadIdx.x;
    const int lane = tid & 31;
    const int wa   = tid >> 5;          // 8 warps
    const int p0   = blockIdx.x * 32;

    if (tid < 32) {
        int c = g_cnt[p0 + tid];
        s_cnt[tid] = (c < KCAP) ? c : KCAP;
        g_cnt[p0 + tid] = 0;            // restore for next batch / replay
    }
    __syncthreads();

    const int tbase = wa * 4;

    int n[4];
    #pragma unroll
    for (int t = 0; t < 4; t++) n[t] = s_cnt[tbase + t];
    int nmax = max(max(n[0], n[1]), max(n[2], n[3]));

    // Lane covers 2 channels: row r -> g_tin + r*64 + lane*2
    const float2* __restrict__ tin2 =
        reinterpret_cast<const float2*>(g_tin) + lane;

    // Entry base: slot i, target t at eb[i*HWSZ + t]
    const uint2* __restrict__ eb = g_ent + (p0 + tbase);

    float2 acc[4];
    float  sw[4];
    #pragma unroll
    for (int t = 0; t < 4; t++) { acc[t] = make_float2(0.f, 0.f); sw[t] = 0.f; }

    // ---- chunk: slots [s0, s0+4) x 4 targets, fully register-resident ----
    #define GATHER_CHUNK(s0)                                                  \
    {                                                                         \
        uint2 e[16];                                                          \
        _Pragma("unroll")                                                     \
        for (int k = 0; k < 16; k++) {                                        \
            int i = (k >> 2) + (s0), t = k & 3;                               \
            e[k] = __ldcs(&eb[(size_t)i * HWSZ + t]);                         \
        }                                                                     \
        float2 v[16];                                                         \
        _Pragma("unroll")                                                     \
        for (int k = 0; k < 16; k++) {                                        \
            int i = (k >> 2) + (s0), t = k & 3;                               \
            unsigned sx = (i < n[t]) ? e[k].x : 0u;                           \
            v[k] = tin2[(size_t)sx * 32];                                     \
        }                                                                     \
        _Pragma("unroll")                                                     \
        for (int k = 0; k < 16; k++) {                                        \
            int i = (k >> 2) + (s0), t = k & 3;                               \
            float wv = (i < n[t]) ? __uint_as_float(e[k].y) : 0.f;            \
            acc[t].x += wv * v[k].x;                                          \
            acc[t].y += wv * v[k].y;                                          \
            sw[t]    += wv;                                                   \
        }                                                                     \
    }

    GATHER_CHUNK(0)
    if (nmax > 4) {
        GATHER_CHUNK(4)
    }
    #undef GATHER_CHUNK

    // Rare tail: n[t] > 8
    if (nmax > 8) {
        #pragma unroll
        for (int t = 0; t < 4; t++) {
            for (int i = 8; i < n[t]; i++) {
                uint2 e  = __ldcs(&eb[(size_t)i * HWSZ + t]);
                float wv = __uint_as_float(e.y);
                float2 v = tin2[(size_t)e.x * 32];
                acc[t].x += wv * v.x;
                acc[t].y += wv * v.y;
                sw[t]    += wv;
            }
        }
    }

    #pragma unroll
    for (int t = 0; t < 4; t++) {
        float inv = (sw[t] == 0.f) ? 1.f : (1.f / sw[t]);
        int   tl  = tbase + t;
        s_out[tl][lane * 2 + 0] = acc[t].x * inv;
        s_out[tl][lane * 2 + 1] = acc[t].y * inv;
    }
    __syncthreads();

    // Coalesced NCHW output: 64 ch x 32 px, streaming stores.
    float* ob = out + p0 + lane;
    #pragma unroll
    for (int k = 0; k < 8; k++) {
        int c = wa + k * 8;
        __stcs(ob + (size_t)c * HWSZ, s_out[lane][c]);
    }
}

// ---------------------------------------------------------------------------
extern "C" void kernel_launch(void* const* d_in, const int* in_sizes, int n_in,
                              void* d_out, int out_size)
{
    const float* inp    = (const float*)d_in[0];
    const float* flow   = (const float*)d_in[1];
    const float* metric = (const float*)d_in[2];
    float* out = (float*)d_out;

    for (int n = 0; n < NB; n++) {
        tb_kernel<<<NTSP + NBLD, 256>>>(
            inp    + (size_t)n * CC * HWSZ,
            flow   + (size_t)n * 2  * HWSZ,
            metric + (size_t)n * HWSZ);
        gather_kernel<<<NGTH, 256>>>(
            out    + (size_t)n * CC * HWSZ);
    }
}

// round 10
// speedup vs baseline: 1.4422x; 1.4422x over previous
#include <cuda_runtime.h>
#include <cstdint>

// Problem constants
#define NB   4
#define CC   64
#define HH   256
#define WW   448
#define HWSZ (HH * WW)            // 114688
#define KCAP 32                   // max entries per target (Poisson(4) tail ~1e-24)

#define NTSP (HWSZ / 32)          // 3584 transpose blocks (32 px each)
#define NBLD (HWSZ / 256)         // 448 build blocks
#define NGTH (HWSZ / 32)          // 3584 gather blocks (32 targets each)

// Scratch (static zero-init; gather re-zeroes g_cnt behind itself so every
// kernel_launch starts from the same state -> graph replays deterministic).
// Entry layout is TRANSPOSED: slot-major, so slot i of target t lives at
// g_ent[i*HWSZ + t] -> coalesced block-wide entry staging in gather.
__device__ float g_tin[(size_t)HWSZ * 64];     // transposed input [pix][64ch] ~29.4 MB
__device__ int   g_cnt[HWSZ];                  // entries per target
__device__ uint2 g_ent[(size_t)KCAP * HWSZ];   // [slot][target] {src_pix, wgt*exp(metric)}

// ---------------------------------------------------------------------------
// Part A: transpose 32 px x 64 ch tile, NCHW -> channel-last.
// ---------------------------------------------------------------------------
__device__ __forceinline__ void transpose_body(
    const float* __restrict__ inp, int p0, float (*s)[65])
{
    const int tid  = threadIdx.x;
    const int lane = tid & 31;
    const int wa   = tid >> 5;

    #pragma unroll
    for (int k = 0; k < 8; k++) {
        int ch = wa + k * 8;
        s[lane][ch] = __ldcs(inp + (size_t)ch * HWSZ + p0 + lane);
    }
    __syncthreads();

    float4* tb = reinterpret_cast<float4*>(g_tin) + (size_t)p0 * 16;
    #pragma unroll
    for (int k = 0; k < 2; k++) {
        int i  = tid + k * 256;
        int px = i >> 4;
        int f4 = i & 15;
        tb[i] = make_float4(s[px][f4 * 4 + 0], s[px][f4 * 4 + 1],
                            s[px][f4 * 4 + 2], s[px][f4 * 4 + 3]);
    }
}

// ---------------------------------------------------------------------------
// Part B: build per-target entry lists (slot-major layout).
// ---------------------------------------------------------------------------
__device__ __forceinline__ void build_body(
    const float* __restrict__ flow,
    const float* __restrict__ metric, int p0)
{
    const int p = p0 + threadIdx.x;
    const int h = p / WW;
    const int w = p - h * WW;

    float fx = __ldcs(flow + p);
    float fy = __ldcs(flow + HWSZ + p);
    float m  = expf(__ldcs(metric + p));

    float xx  = (float)w + fx;
    float yy  = (float)h + fy;
    float x0f = floorf(xx);
    float y0f = floorf(yy);
    int   x0  = (int)x0f;
    int   y0  = (int)y0f;
    float ax  = xx - x0f;
    float ay  = yy - y0f;

    float wgt[4];
    wgt[0] = (1.f - ax) * (1.f - ay);
    wgt[1] = ax * (1.f - ay);
    wgt[2] = (1.f - ax) * ay;
    wgt[3] = ax * ay;

    #pragma unroll
    for (int j = 0; j < 4; j++) {
        int xi = x0 + (j & 1);
        int yi = y0 + (j >> 1);
        if (((unsigned)xi < (unsigned)WW) && ((unsigned)yi < (unsigned)HH)) {
            int t   = yi * WW + xi;
            int pos = atomicAdd(&g_cnt[t], 1);
            if (pos < KCAP) {
                g_ent[(size_t)pos * HWSZ + t] =
                    make_uint2((unsigned)p, __float_as_uint(wgt[j] * m));
            }
        }
    }
}

// ---------------------------------------------------------------------------
// Fused transpose+build (independent work, disjoint outputs).
// ---------------------------------------------------------------------------
__global__ __launch_bounds__(256) void tb_kernel(
    const float* __restrict__ inp,
    const float* __restrict__ flow,
    const float* __restrict__ metric)
{
    __shared__ float s[32][65];
    if (blockIdx.x < NTSP) {
        transpose_body(inp, blockIdx.x * 32, s);
    } else {
        build_body(flow, metric, (blockIdx.x - NTSP) * 256);
    }
}

// ---------------------------------------------------------------------------
// Gather: 32 targets per block (8 warps x 4 targets).
// Entries for all 8 slots x 32 targets are staged to smem block-wide with
// perfectly coalesced loads (slot-major layout), so the per-entry dependency
// chain is LDS -> LDG: the 234-cyc global entry load is out of the chain.
// __launch_bounds__(256,4) (<=64 regs, 50% occ) lets each warp pipeline a
// chunk of 16 independent data loads (slots 0-3 x 4 targets) into registers;
// slots 4-7 run under a warp-uniform nmax guard. Dead slots use selp weight 0
// + row-0 redirect (L1-resident). No atomics. Re-zeroes g_cnt behind itself.
// ---------------------------------------------------------------------------
__global__ __launch_bounds__(256, 4) void gather_kernel(float* __restrict__ out)
{
    __shared__ float s_out[32][65];
    __shared__ int   s_cnt[32];
    __shared__ uint2 s_ent[8][32];     // [slot][target], 2 KB

    const int tid  = threadIdx.x;
    const int lane = tid & 31;
    const int wa   = tid >> 5;          // 8 warps
    const int p0   = blockIdx.x * 32;

    if (tid < 32) {
        int c = g_cnt[p0 + tid];
        s_cnt[tid] = (c < KCAP) ? c : KCAP;
        g_cnt[p0 + tid] = 0;            // restore for next batch / replay
    }
    // Stage slots 0-7 x 32 targets: thread tid -> slot wa, target lane.
    s_ent[wa][lane] = __ldcs(&g_ent[(size_t)wa * HWSZ + p0 + lane]);
    __syncthreads();

    const int tbase = wa * 4;

    int n[4];
    #pragma unroll
    for (int t = 0; t < 4; t++) n[t] = s_cnt[tbase + t];
    int nmax = max(max(n[0], n[1]), max(n[2], n[3]));

    // Lane covers 2 channels: row r -> g_tin + r*64 + lane*2
    const float2* __restrict__ tin2 =
        reinterpret_cast<const float2*>(g_tin) + lane;

    float2 acc[4];
    float  sw[4];
    #pragma unroll
    for (int t = 0; t < 4; t++) { acc[t] = make_float2(0.f, 0.f); sw[t] = 0.f; }

    // ---- chunk: slots [s0, s0+4) x 4 targets; entries from smem ----
    #define GATHER_CHUNK(s0)                                                  \
    {                                                                         \
        float2 v[16];                                                         \
        float  wv[16];                                                        \
        _Pragma("unroll")                                                     \
        for (int k = 0; k < 16; k++) {                                        \
            int i = (k >> 2) + (s0), t = k & 3;                               \
            uint2 e  = s_ent[i][tbase + t];                                   \
            bool liv = (i < n[t]);                                            \
            wv[k] = liv ? __uint_as_float(e.y) : 0.f;                         \
            unsigned sx = liv ? e.x : 0u;                                     \
            v[k] = tin2[(size_t)sx * 32];                                     \
        }                                                                     \
        _Pragma("unroll")                                                     \
        for (int k = 0; k < 16; k++) {                                        \
            int t = k & 3;                                                    \
            acc[t].x += wv[k] * v[k].x;                                       \
            acc[t].y += wv[k] * v[k].y;                                       \
            sw[t]    += wv[k];                                                \
        }                                                                     \
    }

    GATHER_CHUNK(0)
    if (nmax > 4) {
        GATHER_CHUNK(4)
    }
    #undef GATHER_CHUNK

    // Rare tail: n[t] > 8 (entries straight from global)
    if (nmax > 8) {
        const uint2* __restrict__ eb = g_ent + (p0 + tbase);
        #pragma unroll
        for (int t = 0; t < 4; t++) {
            for (int i = 8; i < n[t]; i++) {
                uint2 e  = __ldcs(&eb[(size_t)i * HWSZ + t]);
                float wv = __uint_as_float(e.y);
                float2 v = tin2[(size_t)e.x * 32];
                acc[t].x += wv * v.x;
                acc[t].y += wv * v.y;
                sw[t]    += wv;
            }
        }
    }

    #pragma unroll
    for (int t = 0; t < 4; t++) {
        float inv = (sw[t] == 0.f) ? 1.f : (1.f / sw[t]);
        int   tl  = tbase + t;
        s_out[tl][lane * 2 + 0] = acc[t].x * inv;
        s_out[tl][lane * 2 + 1] = acc[t].y * inv;
    }
    __syncthreads();

    // Coalesced NCHW output: 64 ch x 32 px, streaming stores.
    float* ob = out + p0 + lane;
    #pragma unroll
    for (int k = 0; k < 8; k++) {
        int c = wa + k * 8;
        __stcs(ob + (size_t)c * HWSZ, s_out[lane][c]);
    }
}

// ---------------------------------------------------------------------------
extern "C" void kernel_launch(void* const* d_in, const int* in_sizes, int n_in,
                              void* d_out, int out_size)
{
    const float* inp    = (const float*)d_in[0];
    const float* flow   = (const float*)d_in[1];
    const float* metric = (const float*)d_in[2];
    float* out = (float*)d_out;

    for (int n = 0; n < NB; n++) {
        tb_kernel<<<NTSP + NBLD, 256>>>(
            inp    + (size_t)n * CC * HWSZ,
            flow   + (size_t)n * 2  * HWSZ,
            metric + (size_t)n * HWSZ);
        gather_kernel<<<NGTH, 256>>>(
            out    + (size_t)n * CC * HWSZ);
    }
}

// round 13
// speedup vs baseline: 1.4592x; 1.0118x over previous
#include <cuda_runtime.h>
#include <cstdint>

// Problem constants
#define NB   4
#define CC   64
#define HH   256
#define WW   448
#define HWSZ (HH * WW)            // 114688
#define KCAP 32                   // max entries per target (Poisson(4) tail ~1e-24)

#define NTSP (HWSZ / 32)          // 3584 transpose blocks (32 px each)
#define NBLD (HWSZ / 256)         // 448 build blocks
#define NGTH (HWSZ / 32)          // 3584 gather blocks (32 targets each)

// Scratch (static zero-init; gather re-zeroes g_cnt behind itself so every
// kernel_launch starts from the same state -> graph replays deterministic).
// Entry layout is TRANSPOSED: slot-major, so slot i of target t lives at
// g_ent[i*HWSZ + t] -> warp-uniform entry loads in gather.
__device__ float g_tin[(size_t)HWSZ * 64];     // transposed input [pix][64ch] ~29.4 MB
__device__ int   g_cnt[HWSZ];                  // entries per target
__device__ uint2 g_ent[(size_t)KCAP * HWSZ];   // [slot][target] {src_pix, wgt*exp(metric)}

// ---------------------------------------------------------------------------
// Part A: transpose 32 px x 64 ch tile, NCHW -> channel-last.
// ---------------------------------------------------------------------------
__device__ __forceinline__ void transpose_body(
    const float* __restrict__ inp, int p0, float (*s)[65])
{
    const int tid  = threadIdx.x;
    const int lane = tid & 31;
    const int wa   = tid >> 5;

    #pragma unroll
    for (int k = 0; k < 8; k++) {
        int ch = wa + k * 8;
        s[lane][ch] = __ldcs(inp + (size_t)ch * HWSZ + p0 + lane);
    }
    __syncthreads();

    float4* tb = reinterpret_cast<float4*>(g_tin) + (size_t)p0 * 16;
    #pragma unroll
    for (int k = 0; k < 2; k++) {
        int i  = tid + k * 256;
        int px = i >> 4;
        int f4 = i & 15;
        tb[i] = make_float4(s[px][f4 * 4 + 0], s[px][f4 * 4 + 1],
                            s[px][f4 * 4 + 2], s[px][f4 * 4 + 3]);
    }
}

// ---------------------------------------------------------------------------
// Part B: build per-target entry lists (slot-major layout).
// ---------------------------------------------------------------------------
__device__ __forceinline__ void build_body(
    const float* __restrict__ flow,
    const float* __restrict__ metric, int p0)
{
    const int p = p0 + threadIdx.x;
    const int h = p / WW;
    const int w = p - h * WW;

    float fx = __ldcs(flow + p);
    float fy = __ldcs(flow + HWSZ + p);
    float m  = expf(__ldcs(metric + p));

    float xx  = (float)w + fx;
    float yy  = (float)h + fy;
    float x0f = floorf(xx);
    float y0f = floorf(yy);
    int   x0  = (int)x0f;
    int   y0  = (int)y0f;
    float ax  = xx - x0f;
    float ay  = yy - y0f;

    float wgt[4];
    wgt[0] = (1.f - ax) * (1.f - ay);
    wgt[1] = ax * (1.f - ay);
    wgt[2] = (1.f - ax) * ay;
    wgt[3] = ax * ay;

    #pragma unroll
    for (int j = 0; j < 4; j++) {
        int xi = x0 + (j & 1);
        int yi = y0 + (j >> 1);
        if (((unsigned)xi < (unsigned)WW) && ((unsigned)yi < (unsigned)HH)) {
            int t   = yi * WW + xi;
            int pos = atomicAdd(&g_cnt[t], 1);
            if (pos < KCAP) {
                g_ent[(size_t)pos * HWSZ + t] =
                    make_uint2((unsigned)p, __float_as_uint(wgt[j] * m));
            }
        }
    }
}

// ---------------------------------------------------------------------------
// Fused transpose+build (independent work, disjoint outputs).
// ---------------------------------------------------------------------------
__global__ __launch_bounds__(256) void tb_kernel(
    const float* __restrict__ inp,
    const float* __restrict__ flow,
    const float* __restrict__ metric)
{
    __shared__ float s[32][65];
    if (blockIdx.x < NTSP) {
        transpose_body(inp, blockIdx.x * 32, s);
    } else {
        build_body(flow, metric, (blockIdx.x - NTSP) * 256);
    }
}

// ---------------------------------------------------------------------------
// Gather (R8 structure, known-good): 32 targets per block (8 warps x 4
// targets), branchless body, warp-uniform entry LDG.64 from the slot-major
// table, selp weight 0 + row-0 redirect for dead slots. ONE change vs R8:
// slots 4-7 only run when this warp's nmax > 4 (~16% of warps), removing
// ~45% of slot iterations. No atomics. Re-zeroes g_cnt behind itself.
// ---------------------------------------------------------------------------
__global__ __launch_bounds__(256) void gather_kernel(float* __restrict__ out)
{
    __shared__ float s_out[32][65];
    __shared__ int   s_cnt[32];

    const int tid  = threadIdx.x;
    const int lane = tid & 31;
    const int wa   = tid >> 5;          // 8 warps
    const int p0   = blockIdx.x * 32;

    if (tid < 32) {
        int c = g_cnt[p0 + tid];
        s_cnt[tid] = (c < KCAP) ? c : KCAP;
        g_cnt[p0 + tid] = 0;            // restore for next batch / replay
    }
    __syncthreads();

    const int tbase = wa * 4;

    int n[4];
    #pragma unroll
    for (int t = 0; t < 4; t++) n[t] = s_cnt[tbase + t];
    const int nmax = max(max(n[0], n[1]), max(n[2], n[3]));

    // Lane covers 2 channels: row r -> g_tin + r*64 + lane*2
    const float2* __restrict__ tin2 =
        reinterpret_cast<const float2*>(g_tin) + lane;

    // Entry base for this warp's 4 targets; slot i, target t at eb[i*HWSZ + t]
    const uint2* __restrict__ eb = g_ent + (p0 + tbase);

    float2 acc[4];
    float  sw[4];
    #pragma unroll
    for (int t = 0; t < 4; t++) { acc[t] = make_float2(0.f, 0.f); sw[t] = 0.f; }

    #pragma unroll
    for (int i = 0; i < 4; i++) {
        #pragma unroll
        for (int t = 0; t < 4; t++) {
            uint2 e   = __ldcs(&eb[(size_t)i * HWSZ + t]);     // warp-uniform
            bool  liv = (i < n[t]);
            float wv  = liv ? __uint_as_float(e.y) : 0.f;      // selp
            unsigned sx = liv ? e.x : 0u;                      // dead -> row 0 (L1 hit)
            float2 v  = tin2[(size_t)sx * 32];
            acc[t].x += wv * v.x;
            acc[t].y += wv * v.y;
            sw[t]    += wv;
        }
    }

    // Slots 4-7: warp-uniform skip (~84% of warps have nmax <= 4)
    if (nmax > 4) {
        #pragma unroll
        for (int i = 4; i < 8; i++) {
            #pragma unroll
            for (int t = 0; t < 4; t++) {
                uint2 e   = __ldcs(&eb[(size_t)i * HWSZ + t]);
                bool  liv = (i < n[t]);
                float wv  = liv ? __uint_as_float(e.y) : 0.f;
                unsigned sx = liv ? e.x : 0u;
                float2 v  = tin2[(size_t)sx * 32];
                acc[t].x += wv * v.x;
                acc[t].y += wv * v.y;
                sw[t]    += wv;
            }
        }
    }

    // Rare tail: n[t] > 8 (P ~ 2% per target)
    if (nmax > 8) {
        #pragma unroll
        for (int t = 0; t < 4; t++) {
            for (int i = 8; i < n[t]; i++) {
                uint2 e  = __ldcs(&eb[(size_t)i * HWSZ + t]);
                float wv = __uint_as_float(e.y);
                float2 v = tin2[(size_t)e.x * 32];
                acc[t].x += wv * v.x;
                acc[t].y += wv * v.y;
                sw[t]    += wv;
            }
        }
    }

    #pragma unroll
    for (int t = 0; t < 4; t++) {
        float inv = (sw[t] == 0.f) ? 1.f : (1.f / sw[t]);
        int   tl  = tbase + t;
        s_out[tl][lane * 2 + 0] = acc[t].x * inv;
        s_out[tl][lane * 2 + 1] = acc[t].y * inv;
    }
    __syncthreads();

    // Coalesced NCHW output: 64 ch x 32 px, streaming stores.
    float* ob = out + p0 + lane;
    #pragma unroll
    for (int k = 0; k < 8; k++) {
        int c = wa + k * 8;
        __stcs(ob + (size_t)c * HWSZ, s_out[lane][c]);
    }
}

// ---------------------------------------------------------------------------
extern "C" void kernel_launch(void* const* d_in, const int* in_sizes, int n_in,
                              void* d_out, int out_size)
{
    const float* inp    = (const float*)d_in[0];
    const float* flow   = (const float*)d_in[1];
    const float* metric = (const float*)d_in[2];
    float* out = (float*)d_out;

    for (int n = 0; n < NB; n++) {
        tb_kernel<<<NTSP + NBLD, 256>>>(
            inp    + (size_t)n * CC * HWSZ,
            flow   + (size_t)n * 2  * HWSZ,
            metric + (size_t)n * HWSZ);
        gather_kernel<<<NGTH, 256>>>(
            out    + (size_t)n * CC * HWSZ);
    }
}

// round 14
// speedup vs baseline: 1.4736x; 1.0098x over previous
#include <cuda_runtime.h>
#include <cstdint>

// Problem constants
#define NB   4
#define CC   64
#define HH   256
#define WW   448
#define HWSZ (HH * WW)            // 114688
#define KCAP 32                   // max entries per target (Poisson(4) tail ~1e-24)

#define NTSP (HWSZ / 32)          // 3584 transpose blocks (32 px each)
#define NBLD (HWSZ / 256)         // 448 build blocks
#define NGTH (HWSZ / 32)          // 3584 gather blocks (32 targets each)

// Scratch (static zero-init; gather re-zeroes g_cnt behind itself so every
// kernel_launch starts from the same state -> graph replays deterministic).
// Entry layout is TRANSPOSED: slot-major, so slot i of target t lives at
// g_ent[i*HWSZ + t] -> adjacent targets' entries share a 128B line.
__device__ float g_tin[(size_t)HWSZ * 64];     // transposed input [pix][64ch] ~29.4 MB
__device__ int   g_cnt[HWSZ];                  // entries per target
__device__ uint2 g_ent[(size_t)KCAP * HWSZ];   // [slot][target] {src_pix, wgt*exp(metric)}

// ---------------------------------------------------------------------------
// Part A: transpose 32 px x 64 ch tile, NCHW -> channel-last.
// ---------------------------------------------------------------------------
__device__ __forceinline__ void transpose_body(
    const float* __restrict__ inp, int p0, float (*s)[65])
{
    const int tid  = threadIdx.x;
    const int lane = tid & 31;
    const int wa   = tid >> 5;

    #pragma unroll
    for (int k = 0; k < 8; k++) {
        int ch = wa + k * 8;
        s[lane][ch] = __ldcs(inp + (size_t)ch * HWSZ + p0 + lane);
    }
    __syncthreads();

    float4* tb = reinterpret_cast<float4*>(g_tin) + (size_t)p0 * 16;
    #pragma unroll
    for (int k = 0; k < 2; k++) {
        int i  = tid + k * 256;
        int px = i >> 4;
        int f4 = i & 15;
        tb[i] = make_float4(s[px][f4 * 4 + 0], s[px][f4 * 4 + 1],
                            s[px][f4 * 4 + 2], s[px][f4 * 4 + 3]);
    }
}

// ---------------------------------------------------------------------------
// Part B: build per-target entry lists (slot-major layout).
// ---------------------------------------------------------------------------
__device__ __forceinline__ void build_body(
    const float* __restrict__ flow,
    const float* __restrict__ metric, int p0)
{
    const int p = p0 + threadIdx.x;
    const int h = p / WW;
    const int w = p - h * WW;

    float fx = __ldcs(flow + p);
    float fy = __ldcs(flow + HWSZ + p);
    float m  = expf(__ldcs(metric + p));

    float xx  = (float)w + fx;
    float yy  = (float)h + fy;
    float x0f = floorf(xx);
    float y0f = floorf(yy);
    int   x0  = (int)x0f;
    int   y0  = (int)y0f;
    float ax  = xx - x0f;
    float ay  = yy - y0f;

    float wgt[4];
    wgt[0] = (1.f - ax) * (1.f - ay);
    wgt[1] = ax * (1.f - ay);
    wgt[2] = (1.f - ax) * ay;
    wgt[3] = ax * ay;

    #pragma unroll
    for (int j = 0; j < 4; j++) {
        int xi = x0 + (j & 1);
        int yi = y0 + (j >> 1);
        if (((unsigned)xi < (unsigned)WW) && ((unsigned)yi < (unsigned)HH)) {
            int t   = yi * WW + xi;
            int pos = atomicAdd(&g_cnt[t], 1);
            if (pos < KCAP) {
                g_ent[(size_t)pos * HWSZ + t] =
                    make_uint2((unsigned)p, __float_as_uint(wgt[j] * m));
            }
        }
    }
}

// ---------------------------------------------------------------------------
// Fused transpose+build (independent work, disjoint outputs).
// ---------------------------------------------------------------------------
__global__ __launch_bounds__(256) void tb_kernel(
    const float* __restrict__ inp,
    const float* __restrict__ flow,
    const float* __restrict__ metric)
{
    __shared__ float s[32][65];
    if (blockIdx.x < NTSP) {
        transpose_body(inp, blockIdx.x * 32, s);
    } else {
        build_body(flow, metric, (blockIdx.x - NTSP) * 256);
    }
}

// ---------------------------------------------------------------------------
// Gather: 32 targets per block (8 warps x 4 targets), HALF-WARP PER TARGET:
// lanes 0-15 serve one target, lanes 16-31 its neighbor, each lane covering
// 4 channels via one LDG.128 (g_tin rows are 256B-aligned). The two targets'
// entries sit 16B apart in the slot-major table -> one LDG.64 per pair, one
// 128B line. Instructions per entry ~halved vs float2 lanes; wavefronts
// unchanged. Dead slots: selp weight 0 + row-0 redirect. Result staging is a
// true float4 array (all STS 16B-aligned -- see R11 misalignment lesson).
// No atomics. Re-zeroes g_cnt behind itself.
// ---------------------------------------------------------------------------
__global__ __launch_bounds__(256) void gather_kernel(float* __restrict__ out)
{
    __shared__ float4 s_out4[32][17];  // [target][chan/4], row 272 B, 8704 B
    __shared__ int    s_cnt[32];

    const int tid  = threadIdx.x;
    const int lane = tid & 31;
    const int wa   = tid >> 5;          // 8 warps
    const int p0   = blockIdx.x * 32;

    if (tid < 32) {
        int c = g_cnt[p0 + tid];
        s_cnt[tid] = (c < KCAP) ? c : KCAP;
        g_cnt[p0 + tid] = 0;            // restore for next batch / replay
    }
    __syncthreads();

    const int tbase = wa * 4;           // this warp: targets tbase .. tbase+3
    const int half  = lane >> 4;        // 0 or 1: which target of the pair
    const int c4    = lane & 15;        // float4 index (channels c4*4..c4*4+3)

    const int n0 = s_cnt[tbase + 0];
    const int n1 = s_cnt[tbase + 1];
    const int n2 = s_cnt[tbase + 2];
    const int n3 = s_cnt[tbase + 3];
    const int nmax = max(max(n0, n1), max(n2, n3));

    // Per-lane entry counts: pair0 = targets {tbase, tbase+1},
    //                        pair1 = targets {tbase+2, tbase+3}
    const int nlA = half ? n1 : n0;
    const int nlB = half ? n3 : n2;

    // Per-lane entry pointers (lanes of a half-warp share the address;
    // the two half-warps' addresses are 16 B apart -> same 128 B line).
    const uint2* __restrict__ ebA = g_ent + p0 + tbase + half;
    const uint2* __restrict__ ebB = g_ent + p0 + tbase + 2 + half;

    const float4* __restrict__ tin4 =
        reinterpret_cast<const float4*>(g_tin);   // row = 16 float4

    float4 accA = make_float4(0.f, 0.f, 0.f, 0.f);
    float4 accB = make_float4(0.f, 0.f, 0.f, 0.f);
    float  swA = 0.f, swB = 0.f;

    #define GPAIR(EB, NL, ACC, SW, I)                                         \
    {                                                                         \
        uint2 e   = __ldcs((EB) + (size_t)(I) * HWSZ);                        \
        bool  liv = ((I) < (NL));                                             \
        float wv  = liv ? __uint_as_float(e.y) : 0.f;                         \
        unsigned sx = liv ? e.x : 0u;                                         \
        float4 v  = tin4[(size_t)sx * 16 + c4];                               \
        (ACC).x += wv * v.x;                                                  \
        (ACC).y += wv * v.y;                                                  \
        (ACC).z += wv * v.z;                                                  \
        (ACC).w += wv * v.w;                                                  \
        (SW)    += wv;                                                        \
    }

    #pragma unroll
    for (int i = 0; i < 4; i++) {
        GPAIR(ebA, nlA, accA, swA, i)
        GPAIR(ebB, nlB, accB, swB, i)
    }

    // Slots 4-7: warp-uniform skip (~84% of warps have nmax <= 4)
    if (nmax > 4) {
        #pragma unroll
        for (int i = 4; i < 8; i++) {
            GPAIR(ebA, nlA, accA, swA, i)
            GPAIR(ebB, nlB, accB, swB, i)
        }
    }

    // Rare tail: n > 8 (P ~ 2% per target)
    if (nmax > 8) {
        const int npA = max(n0, n1);
        const int npB = max(n2, n3);
        for (int i = 8; i < npA; i++) GPAIR(ebA, nlA, accA, swA, i)
        for (int i = 8; i < npB; i++) GPAIR(ebB, nlB, accB, swB, i)
    }
    #undef GPAIR

    const float invA = (swA == 0.f) ? 1.f : (1.f / swA);
    const float invB = (swB == 0.f) ? 1.f : (1.f / swB);
    s_out4[tbase + half][c4] =
        make_float4(accA.x * invA, accA.y * invA, accA.z * invA, accA.w * invA);
    s_out4[tbase + 2 + half][c4] =
        make_float4(accB.x * invB, accB.y * invB, accB.z * invB, accB.w * invB);
    __syncthreads();

    // Coalesced NCHW output: 64 ch x 32 px, streaming stores.
    const float* s = reinterpret_cast<const float*>(s_out4);
    float* ob = out + p0 + lane;
    #pragma unroll
    for (int k = 0; k < 8; k++) {
        int c = wa + k * 8;
        __stcs(ob + (size_t)c * HWSZ, s[lane * 68 + c]);
    }
}

// ---------------------------------------------------------------------------
extern "C" void kernel_launch(void* const* d_in, const int* in_sizes, int n_in,
                              void* d_out, int out_size)
{
    const float* inp    = (const float*)d_in[0];
    const float* flow   = (const float*)d_in[1];
    const float* metric = (const float*)d_in[2];
    float* out = (float*)d_out;

    for (int n = 0; n < NB; n++) {
        tb_kernel<<<NTSP + NBLD, 256>>>(
            inp    + (size_t)n * CC * HWSZ,
            flow   + (size_t)n * 2  * HWSZ,
            metric + (size_t)n * HWSZ);
        gather_kernel<<<NGTH, 256>>>(
            out    + (size_t)n * CC * HWSZ);
    }
}